// round 9
// baseline (speedup 1.0000x reference)
#include <cuda_runtime.h>
#include <cuda_fp16.h>
#include <math.h>
#include <stdint.h>

// Problem constants
#define N_INST 16384
#define BAGS   64
#define NMC    4
#define RF     512
#define D0     1024
#define D1     512
#define D2     256
#define NATT   4
#define DATT   32

// ---------------------------------------------------------------------------
// Scratch (static device globals: allocation-guard safe)
// ---------------------------------------------------------------------------
__device__ float g_z   [(size_t)NMC * N_INST * RF];
__device__ float g_expP[(size_t)N_INST * NMC * NATT];
__device__ float g_seg [BAGS * NMC * NATT];

__device__ __half g_Xh  [(size_t)N_INST * D0];
__device__ __half g_phih[(size_t)NMC * N_INST * 2 * RF];
__device__ __half g_h1h [(size_t)NMC * N_INST * D1];
__device__ __half g_embh[(size_t)NMC * N_INST * D2];
__device__ __half g_embl[(size_t)NMC * N_INST * D2];
// fp16 weights, TRANSPOSED [N][K]
__device__ __half g_O1T[(size_t)NMC * RF * D0];
__device__ __half g_O2T[(size_t)NMC * RF * D1];
__device__ __half g_W1T[(size_t)D1 * 2 * RF];
__device__ __half g_W2T[(size_t)D2 * 2 * RF];
__device__ __half g_WmT[(size_t)(NATT * DATT) * D2];

// ---------------------------------------------------------------------------
// Helpers
// ---------------------------------------------------------------------------
__device__ __forceinline__ void h_split(float v, __half& hi, __half& lo) {
    hi = __float2half_rn(v);
    lo = __float2half_rn(v - __half2float(hi));
}

#define CP_ASYNC16(smem_u32, gptr) \
    asm volatile("cp.async.cg.shared.global [%0], [%1], 16;\n" \
                 :: "r"(smem_u32), "l"(gptr))
#define CP_COMMIT()  asm volatile("cp.async.commit_group;\n")
#define CP_WAIT(n)   asm volatile("cp.async.wait_group %0;\n" :: "n"(n))

#define MMA_F16(c, a0, a1, a2, a3, b0, b1) \
    asm volatile("mma.sync.aligned.m16n8k16.row.col.f32.f16.f16.f32 " \
                 "{%0,%1,%2,%3}, {%4,%5,%6,%7}, {%8,%9}, {%0,%1,%2,%3};" \
                 : "+f"((c)[0]), "+f"((c)[1]), "+f"((c)[2]), "+f"((c)[3]) \
                 : "r"(a0), "r"(a1), "r"(a2), "r"(a3), "r"(b0), "r"(b1))

#define LDSM4(r0, r1, r2, r3, addr) \
    asm volatile("ldmatrix.sync.aligned.m8n8.x4.shared.b16 {%0,%1,%2,%3}, [%4];" \
                 : "=r"(r0), "=r"(r1), "=r"(r2), "=r"(r3) : "r"(addr))

// ---------------------------------------------------------------------------
// fp16 tensor-core GEMM, TERMS=1 (pure fp16) or TERMS=2 (A hi/lo split).
// C[M,N] = A[M,K] @ B^T (+bias); B TRANSPOSED [N][K].
// Block tile 128x128x32, 256 threads, warp tile 32x64.
// 3-stage cp.async pipeline (prefetch 2 ahead); LDK=40 conflict-free.
// ---------------------------------------------------------------------------
#define TBM 128
#define TBN 128
#define TBK 32
#define LDK 40
#define TILE_ELEMS (128 * LDK)
#define NBUF 3

template<int TERMS>
__global__ __launch_bounds__(256, 2) void f16_gemm(
    const __half* __restrict__ Ah, const __half* __restrict__ Al,
    const __half* __restrict__ BhT,
    const float* __restrict__ bias,
    float* __restrict__ C, __half* __restrict__ Chi, __half* __restrict__ Clo,
    int M, int Ncols, int K,
    long long sA, long long sB, long long sC)
{
    constexpr int NT = TERMS + 1;            // tiles per stage: A(h[,l]), B
    constexpr int STAGE_ELEMS = NT * TILE_ELEMS;
    constexpr int B_TILE = TERMS;

    Ah  += (long long)blockIdx.z * sA;
    if (TERMS == 2) Al += (long long)blockIdx.z * sA;
    BhT += (long long)blockIdx.z * sB;
    if (C)   C   += (long long)blockIdx.z * sC;
    if (Chi) Chi += (long long)blockIdx.z * sC;
    if (Clo) Clo += (long long)blockIdx.z * sC;

    extern __shared__ __half smem[];

    const int tid  = threadIdx.x;
    const int wid  = tid >> 5;
    const int lane = tid & 31;
    const int wm   = (wid >> 1) * 32;
    const int wn   = (wid & 1) * 64;
    const int brow = blockIdx.y * TBM;
    const int bcol = blockIdx.x * TBN;
    const int lg   = lane >> 2;
    const int lq2  = (lane & 3) * 2;

    float acc[2][8][4];
#pragma unroll
    for (int mi = 0; mi < 2; mi++)
#pragma unroll
        for (int ni = 0; ni < 8; ni++)
#pragma unroll
            for (int j = 0; j < 4; j++) acc[mi][ni][j] = 0.f;

    const int nStages = K / TBK;
    const uint32_t smemBase = (uint32_t)__cvta_generic_to_shared(smem);

    const int stR = tid >> 1;
    const int stC = (tid & 1) * 16;

    auto stage_cpasync = [&](int buf, int k0) {
        const uint32_t sbb = smemBase + buf * (STAGE_ELEMS * 2);
#pragma unroll
        for (int i = 0; i < 2; i++) {
            const int c = stC + i * 8;
            CP_ASYNC16(sbb + (0 * TILE_ELEMS + stR * LDK + c) * 2,
                       Ah + (long long)(brow + stR) * K + k0 + c);
            if (TERMS == 2)
                CP_ASYNC16(sbb + (1 * TILE_ELEMS + stR * LDK + c) * 2,
                           Al + (long long)(brow + stR) * K + k0 + c);
            CP_ASYNC16(sbb + (B_TILE * TILE_ELEMS + stR * LDK + c) * 2,
                       BhT + (long long)(bcol + stR) * K + k0 + c);
        }
        CP_COMMIT();
    };

    const uint32_t aOff =
        (uint32_t)(((lane & 15) * LDK + (lane >> 4) * 8) * 2);
    const uint32_t bOff =
        (uint32_t)((((lane & 7) + ((lane >> 4) << 3)) * LDK +
                    (((lane >> 3) & 1) << 3)) * 2);

    stage_cpasync(0, 0);
    if (nStages > 1) stage_cpasync(1, TBK);

    int buf = 0;
    for (int s = 0; s < nStages; s++) {
        if (s + 2 < nStages) {
            stage_cpasync((s + 2) % NBUF, (s + 2) * TBK);
            CP_WAIT(2);
        } else if (s + 1 < nStages) {
            CP_WAIT(1);
        } else {
            CP_WAIT(0);
        }
        __syncthreads();

        const uint32_t tb  = smemBase + buf * (STAGE_ELEMS * 2);
        const uint32_t AhB = tb;
        const uint32_t AlB = tb + TILE_ELEMS * 2;
        const uint32_t BhB = tb + B_TILE * TILE_ELEMS * 2;

#pragma unroll
        for (int kk = 0; kk < 2; kk++) {
            const uint32_t kByte = kk * 16 * 2;
            uint32_t ah[2][4], al[2][4];
#pragma unroll
            for (int mi = 0; mi < 2; mi++) {
                const uint32_t rowB = (uint32_t)((wm + mi * 16) * LDK * 2);
                LDSM4(ah[mi][0], ah[mi][1], ah[mi][2], ah[mi][3],
                      AhB + rowB + aOff + kByte);
                if (TERMS == 2)
                    LDSM4(al[mi][0], al[mi][1], al[mi][2], al[mi][3],
                          AlB + rowB + aOff + kByte);
            }
#pragma unroll
            for (int p = 0; p < 4; p++) {
                const uint32_t nB = (uint32_t)((wn + p * 16) * LDK * 2);
                uint32_t bh0, bh1, bh2, bh3;
                LDSM4(bh0, bh1, bh2, bh3, BhB + nB + bOff + kByte);
#pragma unroll
                for (int mi = 0; mi < 2; mi++) {
                    float* c0 = acc[mi][p * 2];
                    float* c1 = acc[mi][p * 2 + 1];
                    MMA_F16(c0, ah[mi][0], ah[mi][1], ah[mi][2], ah[mi][3], bh0, bh1);
                    MMA_F16(c1, ah[mi][0], ah[mi][1], ah[mi][2], ah[mi][3], bh2, bh3);
                    if (TERMS == 2) {
                        MMA_F16(c0, al[mi][0], al[mi][1], al[mi][2], al[mi][3], bh0, bh1);
                        MMA_F16(c1, al[mi][0], al[mi][1], al[mi][2], al[mi][3], bh2, bh3);
                    }
                }
            }
        }
        __syncthreads();
        buf = (buf + 1 == NBUF) ? 0 : buf + 1;
    }

    // Epilogue
#pragma unroll
    for (int mi = 0; mi < 2; mi++) {
        const int row0 = brow + wm + mi * 16 + lg;
#pragma unroll
        for (int ni = 0; ni < 8; ni++) {
            const int col = bcol + wn + ni * 8 + lq2;
            float b0 = 0.f, b1 = 0.f;
            if (bias) { b0 = bias[col]; b1 = bias[col + 1]; }
            float v0 = acc[mi][ni][0] + b0;
            float v1 = acc[mi][ni][1] + b1;
            float v2 = acc[mi][ni][2] + b0;
            float v3 = acc[mi][ni][3] + b1;
            if (C) {
                *(float2*)(C + (long long)row0 * Ncols + col)       = make_float2(v0, v1);
                *(float2*)(C + (long long)(row0 + 8) * Ncols + col) = make_float2(v2, v3);
            }
            if (Chi && !Clo) {
                *(__half2*)(Chi + (long long)row0 * Ncols + col) =
                    __halves2half2(__float2half_rn(v0), __float2half_rn(v1));
                *(__half2*)(Chi + (long long)(row0 + 8) * Ncols + col) =
                    __halves2half2(__float2half_rn(v2), __float2half_rn(v3));
            } else if (Chi) {
                __half h0, l0, h1, l1, h2, l2, h3, l3;
                h_split(v0, h0, l0); h_split(v1, h1, l1);
                h_split(v2, h2, l2); h_split(v3, h3, l3);
                *(__half2*)(Chi + (long long)row0 * Ncols + col)       = __halves2half2(h0, h1);
                *(__half2*)(Clo + (long long)row0 * Ncols + col)       = __halves2half2(l0, l1);
                *(__half2*)(Chi + (long long)(row0 + 8) * Ncols + col) = __halves2half2(h2, h3);
                *(__half2*)(Clo + (long long)(row0 + 8) * Ncols + col) = __halves2half2(l2, l3);
            }
        }
    }
}

#define SMEM_T1 (NBUF * 2 * TILE_ELEMS * 2)   // 61440
#define SMEM_T2 (NBUF * 3 * TILE_ELEMS * 2)   // 92160

// ---------------------------------------------------------------------------
__global__ __launch_bounds__(256) void cvt_kernel(
    const float* __restrict__ src, __half* __restrict__ dst, long long n)
{
    long long i = (long long)blockIdx.x * blockDim.x + threadIdx.x;
    if (i < n) dst[i] = __float2half_rn(src[i]);
}

// fp32 [K][N] -> transposed fp16 [N][K], 32x32 smem-tiled.
__global__ __launch_bounds__(256) void splitT_kernel(
    const float* __restrict__ src, __half* __restrict__ hT, int K, int N)
{
    __shared__ float t[32][33];
    const long long boff = (long long)blockIdx.z * K * N;
    const int k0 = blockIdx.x * 32;
    const int n0 = blockIdx.y * 32;
    const int tx = threadIdx.x, ty = threadIdx.y;

#pragma unroll
    for (int i = 0; i < 32; i += 8)
        t[ty + i][tx] = src[boff + (long long)(k0 + ty + i) * N + n0 + tx];
    __syncthreads();
#pragma unroll
    for (int i = 0; i < 32; i += 8)
        hT[boff + (long long)(n0 + ty + i) * K + k0 + tx] =
            __float2half_rn(t[tx][ty + i]);
}

// ---------------------------------------------------------------------------
// Fused RBF random features + LayerNorm; writes fp16 phi.
// ---------------------------------------------------------------------------
__global__ __launch_bounds__(256) void rfln_kernel(
    const float* __restrict__ z, __half* __restrict__ phih)
{
    const long long row = blockIdx.x;
    const float* zr = z + row * RF;
    __half* ph = phih + row * (2 * RF);
    const int t = threadIdx.x;
    const float scale = 0.044194173824159216f;  // 1/sqrt(512)

    float za = zr[t];
    float zb = zr[t + 256];
    float ca = __cosf(za) * scale;
    float sa = __sinf(za) * scale;
    float cb = __cosf(zb) * scale;
    float sb2 = __sinf(zb) * scale;

    float sum = ca + cb + sa + sb2;
    float sq  = ca * ca + cb * cb + sa * sa + sb2 * sb2;

#pragma unroll
    for (int o = 16; o > 0; o >>= 1) {
        sum += __shfl_down_sync(0xffffffffu, sum, o);
        sq  += __shfl_down_sync(0xffffffffu, sq,  o);
    }
    __shared__ float s_sum[8], s_sq[8];
    __shared__ float s_mean, s_inv;
    const int warp = t >> 5, lane = t & 31;
    if (lane == 0) { s_sum[warp] = sum; s_sq[warp] = sq; }
    __syncthreads();
    if (t == 0) {
        float ts = 0.f, tq = 0.f;
#pragma unroll
        for (int i = 0; i < 8; i++) { ts += s_sum[i]; tq += s_sq[i]; }
        float mean = ts * (1.f / 1024.f);
        float var  = tq * (1.f / 1024.f) - mean * mean;
        s_mean = mean;
        s_inv  = rsqrtf(var + 1e-5f);
    }
    __syncthreads();
    const float mean = s_mean, inv = s_inv;
    ph[t]       = __float2half_rn((ca  - mean) * inv);
    ph[t + 256] = __float2half_rn((cb  - mean) * inv);
    ph[t + 512] = __float2half_rn((sa  - mean) * inv);
    ph[t + 768] = __float2half_rn((sb2 - mean) * inv);
}

// ---------------------------------------------------------------------------
// Attention scores from fp16 emb (hi part) + per-bag exp-sum (atomics).
// ---------------------------------------------------------------------------
__global__ __launch_bounds__(256) void scores_kernel(
    const __half* __restrict__ embh, const float* __restrict__ Ws,
    const float* __restrict__ bs, const int* __restrict__ idx,
    float* __restrict__ expP, float* __restrict__ seg)
{
    const int gw   = (blockIdx.x * blockDim.x + threadIdx.x) >> 5;
    const int lane = threadIdx.x & 31;
    if (gw >= NMC * N_INST) return;
    const int m = gw / N_INST;
    const int n = gw - m * N_INST;
    const __half2* e = (const __half2*)(embh + (long long)gw * D2);

    float a0 = 0.f, a1 = 0.f, a2 = 0.f, a3 = 0.f;
    for (int d = lane; d < D2 / 2; d += 32) {
        __half2 ev = e[d];
        float e0 = __low2float(ev), e1 = __high2float(ev);
        float4 w0 = *(const float4*)(Ws + (2 * d) * 4);
        float4 w1 = *(const float4*)(Ws + (2 * d + 1) * 4);
        a0 = fmaf(e0, w0.x, fmaf(e1, w1.x, a0));
        a1 = fmaf(e0, w0.y, fmaf(e1, w1.y, a1));
        a2 = fmaf(e0, w0.z, fmaf(e1, w1.z, a2));
        a3 = fmaf(e0, w0.w, fmaf(e1, w1.w, a3));
    }
#pragma unroll
    for (int o = 16; o > 0; o >>= 1) {
        a0 += __shfl_down_sync(0xffffffffu, a0, o);
        a1 += __shfl_down_sync(0xffffffffu, a1, o);
        a2 += __shfl_down_sync(0xffffffffu, a2, o);
        a3 += __shfl_down_sync(0xffffffffu, a3, o);
    }
    if (lane == 0) {
        const int b = idx[n];
        const float inv16 = 0.0625f;  // 1/sqrt(D2)
        float v0 = expf((a0 + bs[0]) * inv16);
        float v1 = expf((a1 + bs[1]) * inv16);
        float v2 = expf((a2 + bs[2]) * inv16);
        float v3 = expf((a3 + bs[3]) * inv16);
        float* ep = expP + ((long long)n * NMC + m) * NATT;
        ep[0] = v0; ep[1] = v1; ep[2] = v2; ep[3] = v3;
        float* sp = seg + ((long long)b * NMC + m) * NATT;
        atomicAdd(sp + 0, v0);
        atomicAdd(sp + 1, v1);
        atomicAdd(sp + 2, v2);
        atomicAdd(sp + 3, v3);
    }
}

// ---------------------------------------------------------------------------
// Weighted segment pooling.
// ---------------------------------------------------------------------------
__global__ __launch_bounds__(128) void pool_kernel(
    const float* __restrict__ embnew, const float* __restrict__ expP,
    const float* __restrict__ seg, const int* __restrict__ idx,
    float* __restrict__ out)
{
    const int m  = blockIdx.y;
    const int n0 = blockIdx.x * 8;
    const int e  = threadIdx.x;
    const int k  = e >> 5;

    float accum = 0.f;
    int   cur   = -1;
#pragma unroll
    for (int r = 0; r < 8; r++) {
        const int n = n0 + r;
        const int b = idx[n];
        float v = embnew[((long long)m * N_INST + n) * (NATT * DATT) + e];
        v = fmaxf(v, 0.f);
        const float p = expP[((long long)n * NMC + m) * NATT + k] /
                        seg [((long long)b * NMC + m) * NATT + k];
        v *= p;
        if (b != cur) {
            if (cur >= 0) atomicAdd(out + ((long long)cur * NMC + m) * (NATT * DATT) + e, accum);
            cur = b;
            accum = v;
        } else {
            accum += v;
        }
    }
    if (cur >= 0) atomicAdd(out + ((long long)cur * NMC + m) * (NATT * DATT) + e, accum);
}

// ---------------------------------------------------------------------------
__global__ void zero_kernel(float* __restrict__ out, float* __restrict__ seg)
{
    const int i = blockIdx.x * blockDim.x + threadIdx.x;
    if (i < BAGS * NMC * NATT * DATT) out[i] = 0.f;
    if (i < BAGS * NMC * NATT)        seg[i] = 0.f;
}

// ---------------------------------------------------------------------------
extern "C" void kernel_launch(void* const* d_in, const int* in_sizes, int n_in,
                              void* d_out, int out_size)
{
    const float* X      = (const float*)d_in[0];
    const int*   X_idx  = (const int*)  d_in[1];
    const float* Omega1 = (const float*)d_in[2];
    const float* Omega2 = (const float*)d_in[3];
    const float* W1     = (const float*)d_in[4];
    const float* b1     = (const float*)d_in[5];
    const float* W2     = (const float*)d_in[6];
    const float* b2     = (const float*)d_in[7];
    const float* Ws     = (const float*)d_in[8];
    const float* bs     = (const float*)d_in[9];
    const float* Wm     = (const float*)d_in[10];
    const float* bm     = (const float*)d_in[11];
    float* out = (float*)d_out;

    static bool cfg = false;
    if (!cfg) {
        cudaFuncSetAttribute(f16_gemm<1>,
                             cudaFuncAttributeMaxDynamicSharedMemorySize, SMEM_T1);
        cudaFuncSetAttribute(f16_gemm<2>,
                             cudaFuncAttributeMaxDynamicSharedMemorySize, SMEM_T2);
        cfg = true;
    }

    float *z, *expP, *seg;
    __half *Xh, *phih, *h1h, *embh, *embl;
    __half *O1T, *O2T, *W1T, *W2T, *WmT;
    cudaGetSymbolAddress((void**)&z,    g_z);
    cudaGetSymbolAddress((void**)&expP, g_expP);
    cudaGetSymbolAddress((void**)&seg,  g_seg);
    cudaGetSymbolAddress((void**)&Xh,   g_Xh);
    cudaGetSymbolAddress((void**)&phih, g_phih);
    cudaGetSymbolAddress((void**)&h1h,  g_h1h);
    cudaGetSymbolAddress((void**)&embh, g_embh);
    cudaGetSymbolAddress((void**)&embl, g_embl);
    cudaGetSymbolAddress((void**)&O1T,  g_O1T);
    cudaGetSymbolAddress((void**)&O2T,  g_O2T);
    cudaGetSymbolAddress((void**)&W1T,  g_W1T);
    cudaGetSymbolAddress((void**)&W2T,  g_W2T);
    cudaGetSymbolAddress((void**)&WmT,  g_WmT);

    // Launch order arranged so the 6th launch (ncu -s 5 -c 1) is GEMM1.
    // 1. zero
    zero_kernel<<<128, 256>>>(out, seg);
    // 2. X -> fp16
    {
        long long nX = (long long)N_INST * D0;
        cvt_kernel<<<(unsigned)((nX + 255) / 256), 256>>>(X, Xh, nX);
    }
    // 3-5. weight transposes needed before GEMM1 (+ two fillers)
    splitT_kernel<<<dim3(D0 / 32, RF / 32, NMC), dim3(32, 8)>>>(Omega1, O1T, D0, RF);
    splitT_kernel<<<dim3((2 * RF) / 32, D1 / 32, 1), dim3(32, 8)>>>(W1, W1T, 2 * RF, D1);
    splitT_kernel<<<dim3(D1 / 32, RF / 32, NMC), dim3(32, 8)>>>(Omega2, O2T, D1, RF);

    // 6. z1[m] = X @ Omega1[m]  [16384,1024]x[1024,512] batched  <-- PROFILED
    {
        dim3 g(RF / TBN, N_INST / TBM, NMC);
        f16_gemm<1><<<g, 256, SMEM_T1>>>(
            Xh, nullptr, O1T, nullptr, z, nullptr, nullptr,
            N_INST, RF, D0,
            0LL, (long long)RF * D0, (long long)N_INST * RF);
    }
    // 7-8. remaining weight transposes
    splitT_kernel<<<dim3((2 * RF) / 32, D2 / 32, 1), dim3(32, 8)>>>(W2, W2T, 2 * RF, D2);
    splitT_kernel<<<dim3(D2 / 32, (NATT * DATT) / 32, 1), dim3(32, 8)>>>(Wm, WmT, D2, NATT * DATT);

    // 9. phi1 = LN(rf(z1))
    rfln_kernel<<<NMC * N_INST, 256>>>(z, phih);

    // 10. h1 = phi1 @ W1 + b1
    {
        dim3 g(D1 / TBN, (NMC * N_INST) / TBM, 1);
        f16_gemm<1><<<g, 256, SMEM_T1>>>(
            phih, nullptr, W1T, b1, nullptr, h1h, nullptr,
            NMC * N_INST, D1, 2 * RF, 0LL, 0LL, 0LL);
    }
    // 11. z2[m] = h1[m] @ Omega2[m]
    {
        dim3 g(RF / TBN, N_INST / TBM, NMC);
        f16_gemm<1><<<g, 256, SMEM_T1>>>(
            h1h, nullptr, O2T, nullptr, z, nullptr, nullptr,
            N_INST, RF, D1,
            (long long)N_INST * D1, (long long)RF * D1, (long long)N_INST * RF);
    }
    // 12. phi2 = LN(rf(z2))
    rfln_kernel<<<NMC * N_INST, 256>>>(z, phih);

    // 13. emb = phi2 @ W2 + b2  -> fp16 hi/lo only
    {
        dim3 g(D2 / TBN, (NMC * N_INST) / TBM, 1);
        f16_gemm<1><<<g, 256, SMEM_T1>>>(
            phih, nullptr, W2T, b2, nullptr, embh, embl,
            NMC * N_INST, D2, 2 * RF, 0LL, 0LL, 0LL);
    }
    // 14. attention scores + segment exp-sums (reads fp16 embh)
    scores_kernel<<<(NMC * N_INST * 32 + 255) / 256, 256>>>(embh, Ws, bs, X_idx, expP, seg);

    // 15. emb_new = emb @ Wm + bm (2-term A split) -> fp32 z
    {
        dim3 g((NATT * DATT) / TBN, (NMC * N_INST) / TBM, 1);
        f16_gemm<2><<<g, 256, SMEM_T2>>>(
            embh, embl, WmT, bm, z, nullptr, nullptr,
            NMC * N_INST, NATT * DATT, D2, 0LL, 0LL, 0LL);
    }
    // 16. relu + softmax weighting + segment pooling
    pool_kernel<<<dim3(N_INST / 8, NMC), 128>>>(z, expP, seg, X_idx, out);
}